// round 15
// baseline (speedup 1.0000x reference)
#include <cuda_runtime.h>
#include <cuda_bf16.h>

#define B_BATCH 8192
#define N_SUP   64
#define D_DIM   256
#define EPS     1e-8f

#define WARPS_PER_CTA 8
#define GRID_CTAS     592   /* 148 SMs x 4 CTAs: perfectly balanced placement */

#define ROW_F4 (D_DIM / 4)

__device__ float g_dist[B_BATCH];
__device__ unsigned int g_counter = 0;   // finished-CTA counter
__device__ unsigned int g_work    = 0;   // row work queue head

// Persistent CTAs; each WARP pulls batch rows from a global queue.
// Next-row atomic is issued at loop top and consumed only after the body
// (software pipelining) so queue latency is hidden under the row's loads.
__global__ __launch_bounds__(256, 4) void proto_loss_kernel(
    const float* __restrict__ query,     // (B, D)
    const float* __restrict__ support,   // (B, N, D)
    const int*   __restrict__ labels,    // (B, N)
    float* __restrict__ out)             // scalar
{
    const int tid  = threadIdx.x;
    const int lane = tid & 31;
    const int wid  = tid >> 5;
    const int c0   = 2 * lane;

    // First grab (latency exposed once per warp)
    unsigned braw = (lane == 0) ? atomicAdd(&g_work, 1u) : 0u;
    unsigned b    = __shfl_sync(0xFFFFFFFFu, braw, 0);

    while (b < B_BATCH) {
        // Issue next grab now; consume at loop end (overlaps with body)
        unsigned nraw = (lane == 0) ? atomicAdd(&g_work, 1u) : 0u;

        const float4* __restrict__ sup4 = reinterpret_cast<const float4*>(
            support + (size_t)b * N_SUP * D_DIM);

        // Label masks: 2 coalesced loads + 2 ballots
        const int lbase = (int)b * N_SUP;
        const unsigned m0 = __ballot_sync(0xFFFFFFFFu, labels[lbase + lane]      == 1);
        const unsigned m1 = __ballot_sync(0xFFFFFFFFu, labels[lbase + 32 + lane] == 1);
        const int cnt = __popc(m0) + __popc(m1);

        // Fully-unrolled dual-stream predicated accumulation (R13 structure).
        // Lane owns dims [8*lane, 8*lane+8); enabled row = 1KB coalesced read.
        float4 a0 = make_float4(0.f, 0.f, 0.f, 0.f);
        float4 a1 = make_float4(0.f, 0.f, 0.f, 0.f);
        float4 e0 = make_float4(0.f, 0.f, 0.f, 0.f);
        float4 e1 = make_float4(0.f, 0.f, 0.f, 0.f);

        #pragma unroll
        for (int n = 0; n < 32; n++) {
            if ((m0 >> n) & 1u) {
                float4 v0 = __ldcs(&sup4[n * ROW_F4 + c0]);
                float4 v1 = __ldcs(&sup4[n * ROW_F4 + c0 + 1]);
                a0.x += v0.x; a0.y += v0.y; a0.z += v0.z; a0.w += v0.w;
                a1.x += v1.x; a1.y += v1.y; a1.z += v1.z; a1.w += v1.w;
            }
            if ((m1 >> n) & 1u) {
                float4 w0 = __ldcs(&sup4[(n + 32) * ROW_F4 + c0]);
                float4 w1 = __ldcs(&sup4[(n + 32) * ROW_F4 + c0 + 1]);
                e0.x += w0.x; e0.y += w0.y; e0.z += w0.z; e0.w += w0.w;
                e1.x += w1.x; e1.y += w1.y; e1.z += w1.z; e1.w += w1.w;
            }
        }
        a0.x += e0.x; a0.y += e0.y; a0.z += e0.z; a0.w += e0.w;
        a1.x += e1.x; a1.y += e1.y; a1.z += e1.z; a1.w += e1.w;

        // Prototype (count==0 fallback to support[b,0,:])
        float4 p0, p1;
        if (cnt > 0) {
            const float inv = 1.0f / (float)cnt;
            p0 = make_float4(a0.x * inv, a0.y * inv, a0.z * inv, a0.w * inv);
            p1 = make_float4(a1.x * inv, a1.y * inv, a1.z * inv, a1.w * inv);
        } else {
            p0 = sup4[c0];
            p1 = sup4[c0 + 1];
        }

        const float4* __restrict__ qry4 = reinterpret_cast<const float4*>(
            query + (size_t)b * D_DIM);
        const float4 q0 = qry4[c0];
        const float4 q1 = qry4[c0 + 1];

        float d;
        {
            float dx = q0.x - p0.x, dy = q0.y - p0.y, dz = q0.z - p0.z, dw = q0.w - p0.w;
            d = dx * dx + dy * dy + dz * dz + dw * dw;
            dx = q1.x - p1.x; dy = q1.y - p1.y; dz = q1.z - p1.z; dw = q1.w - p1.w;
            d += dx * dx + dy * dy + dz * dz + dw * dw;
        }
        #pragma unroll
        for (int off = 16; off > 0; off >>= 1)
            d += __shfl_xor_sync(0xFFFFFFFFu, d, off);

        if (lane == 0) g_dist[b] = sqrtf(d + EPS);

        // Consume prefetched row index (atomic latency already overlapped)
        b = __shfl_sync(0xFFFFFFFFu, nraw, 0);
    }

    // ---- last-CTA mean reduce (deterministic fixed-order sum) ----
    __threadfence();
    __syncthreads();
    __shared__ int s_last;
    __shared__ float s_red[WARPS_PER_CTA];
    if (tid == 0)
        s_last = (atomicAdd(&g_counter, 1u) == (unsigned)(GRID_CTAS - 1));
    __syncthreads();

    if (s_last) {
        float s = 0.f;
        #pragma unroll
        for (int i = 0; i < B_BATCH / 256; i++)
            s += g_dist[tid + i * 256];

        #pragma unroll
        for (int off = 16; off > 0; off >>= 1)
            s += __shfl_xor_sync(0xFFFFFFFFu, s, off);
        if (lane == 0) s_red[wid] = s;
        __syncthreads();
        if (tid < WARPS_PER_CTA) {
            float w = s_red[tid];
            #pragma unroll
            for (int off = WARPS_PER_CTA / 2; off > 0; off >>= 1)
                w += __shfl_xor_sync(0xFFu, w, off);
            if (tid == 0) {
                out[0] = w * (1.0f / (float)B_BATCH);
                g_counter = 0;   // reset for next graph replay
                g_work    = 0;   // reset work queue
            }
        }
    }
}

extern "C" void kernel_launch(void* const* d_in, const int* in_sizes, int n_in,
                              void* d_out, int out_size)
{
    const float* query   = (const float*)d_in[0];
    const float* support = (const float*)d_in[1];
    const int*   labels  = (const int*)d_in[2];
    float* out = (float*)d_out;

    proto_loss_kernel<<<GRID_CTAS, 256>>>(query, support, labels, out);
}

// round 16
// speedup vs baseline: 1.0829x; 1.0829x over previous
#include <cuda_runtime.h>
#include <cuda_bf16.h>

#define B_BATCH 8192
#define N_SUP   64
#define D_DIM   256
#define EPS     1e-8f

#define WARPS_PER_CTA 8
#define GRID_CTAS     592                       /* 148 SMs x 4 CTA slots */
#define TOTAL_WARPS   (GRID_CTAS * WARPS_PER_CTA)  /* 4736 */

#define ROW_F4 (D_DIM / 4)

__device__ float g_dist[B_BATCH];
__device__ unsigned int g_counter = 0;

// Grid fills every SM's 4 CTA slots exactly once (no placement raggedness).
// Each warp statically strides rows: b = gw, gw + 4736 (compile-time stride
// -> addresses computable up front, LDG front-batching preserved).
__global__ __launch_bounds__(256, 4) void proto_loss_kernel(
    const float* __restrict__ query,     // (B, D)
    const float* __restrict__ support,   // (B, N, D)
    const int*   __restrict__ labels,    // (B, N)
    float* __restrict__ out)             // scalar
{
    const int tid  = threadIdx.x;
    const int lane = tid & 31;
    const int wid  = tid >> 5;
    const int gw   = blockIdx.x * WARPS_PER_CTA + wid;   // 0..4735
    const int c0   = 2 * lane;

    #pragma unroll 1
    for (int b = gw; b < B_BATCH; b += TOTAL_WARPS) {
        const float4* __restrict__ sup4 = reinterpret_cast<const float4*>(
            support + (size_t)b * N_SUP * D_DIM);

        // Label masks: 2 coalesced loads + 2 ballots.
        const int lbase = b * N_SUP;
        const unsigned m0 = __ballot_sync(0xFFFFFFFFu, labels[lbase + lane]      == 1);
        const unsigned m1 = __ballot_sync(0xFFFFFFFFu, labels[lbase + 32 + lane] == 1);
        const int cnt = __popc(m0) + __popc(m1);

        // Fully-unrolled dual-stream predicated accumulation (R13 structure).
        // Lane owns dims [8*lane, 8*lane+8); enabled row = 1KB coalesced read.
        float4 a0 = make_float4(0.f, 0.f, 0.f, 0.f);
        float4 a1 = make_float4(0.f, 0.f, 0.f, 0.f);
        float4 e0 = make_float4(0.f, 0.f, 0.f, 0.f);
        float4 e1 = make_float4(0.f, 0.f, 0.f, 0.f);

        #pragma unroll
        for (int n = 0; n < 32; n++) {
            if ((m0 >> n) & 1u) {
                float4 v0 = __ldcs(&sup4[n * ROW_F4 + c0]);
                float4 v1 = __ldcs(&sup4[n * ROW_F4 + c0 + 1]);
                a0.x += v0.x; a0.y += v0.y; a0.z += v0.z; a0.w += v0.w;
                a1.x += v1.x; a1.y += v1.y; a1.z += v1.z; a1.w += v1.w;
            }
            if ((m1 >> n) & 1u) {
                float4 w0 = __ldcs(&sup4[(n + 32) * ROW_F4 + c0]);
                float4 w1 = __ldcs(&sup4[(n + 32) * ROW_F4 + c0 + 1]);
                e0.x += w0.x; e0.y += w0.y; e0.z += w0.z; e0.w += w0.w;
                e1.x += w1.x; e1.y += w1.y; e1.z += w1.z; e1.w += w1.w;
            }
        }
        a0.x += e0.x; a0.y += e0.y; a0.z += e0.z; a0.w += e0.w;
        a1.x += e1.x; a1.y += e1.y; a1.z += e1.z; a1.w += e1.w;

        // Prototype (count==0 fallback to support[b,0,:])
        float4 p0, p1;
        if (cnt > 0) {
            const float inv = 1.0f / (float)cnt;
            p0 = make_float4(a0.x * inv, a0.y * inv, a0.z * inv, a0.w * inv);
            p1 = make_float4(a1.x * inv, a1.y * inv, a1.z * inv, a1.w * inv);
        } else {
            p0 = sup4[c0];
            p1 = sup4[c0 + 1];
        }

        const float4* __restrict__ qry4 = reinterpret_cast<const float4*>(
            query + (size_t)b * D_DIM);
        const float4 q0 = qry4[c0];
        const float4 q1 = qry4[c0 + 1];

        float d;
        {
            float dx = q0.x - p0.x, dy = q0.y - p0.y, dz = q0.z - p0.z, dw = q0.w - p0.w;
            d = dx * dx + dy * dy + dz * dz + dw * dw;
            dx = q1.x - p1.x; dy = q1.y - p1.y; dz = q1.z - p1.z; dw = q1.w - p1.w;
            d += dx * dx + dy * dy + dz * dz + dw * dw;
        }
        #pragma unroll
        for (int off = 16; off > 0; off >>= 1)
            d += __shfl_xor_sync(0xFFFFFFFFu, d, off);

        if (lane == 0) g_dist[b] = sqrtf(d + EPS);
    }

    // ---- last-CTA mean reduce (deterministic fixed-order sum) ----
    __threadfence();
    __syncthreads();
    __shared__ int s_last;
    __shared__ float s_red[WARPS_PER_CTA];
    if (tid == 0)
        s_last = (atomicAdd(&g_counter, 1u) == (unsigned)(GRID_CTAS - 1));
    __syncthreads();

    if (s_last) {
        float s = 0.f;
        #pragma unroll
        for (int i = 0; i < B_BATCH / 256; i++)
            s += g_dist[tid + i * 256];

        #pragma unroll
        for (int off = 16; off > 0; off >>= 1)
            s += __shfl_xor_sync(0xFFFFFFFFu, s, off);
        if (lane == 0) s_red[wid] = s;
        __syncthreads();
        if (tid < WARPS_PER_CTA) {
            float w = s_red[tid];
            #pragma unroll
            for (int off = WARPS_PER_CTA / 2; off > 0; off >>= 1)
                w += __shfl_xor_sync(0xFFu, w, off);
            if (tid == 0) {
                out[0] = w * (1.0f / (float)B_BATCH);
                g_counter = 0;   // reset for next graph replay
            }
        }
    }
}

extern "C" void kernel_launch(void* const* d_in, const int* in_sizes, int n_in,
                              void* d_out, int out_size)
{
    const float* query   = (const float*)d_in[0];
    const float* support = (const float*)d_in[1];
    const int*   labels  = (const int*)d_in[2];
    float* out = (float*)d_out;

    proto_loss_kernel<<<GRID_CTAS, 256>>>(query, support, labels, out);
}

// round 17
// speedup vs baseline: 1.0983x; 1.0141x over previous
#include <cuda_runtime.h>
#include <cuda_bf16.h>

#define B_BATCH 8192
#define N_SUP   64
#define D_DIM   256
#define EPS     1e-8f

#define CTA_THREADS   128
#define WARPS_PER_CTA 4
#define ROWS_PER_WARP 2
#define GRID_CTAS     (B_BATCH / (WARPS_PER_CTA * ROWS_PER_WARP))   // 1024

#define ROW_F4 (D_DIM / 4)

__device__ float g_dist[B_BATCH];
__device__ unsigned int g_counter = 0;

// R13's exact per-warp work (2 adjacent rows, sequential, fully-unrolled
// predicated accumulation) but packed into 128-thread CTAs: 8 CTAs/SM, so
// 1024 CTAs spread 6.92/SM -> ~1% per-SM load spread instead of 33%.
__global__ __launch_bounds__(CTA_THREADS, 8) void proto_loss_kernel(
    const float* __restrict__ query,     // (B, D)
    const float* __restrict__ support,   // (B, N, D)
    const int*   __restrict__ labels,    // (B, N)
    float* __restrict__ out)             // scalar
{
    const int tid  = threadIdx.x;
    const int lane = tid & 31;
    const int wid  = tid >> 5;
    const int gw   = blockIdx.x * WARPS_PER_CTA + wid;   // 0..4095
    const int c0   = 2 * lane;

    #pragma unroll 1
    for (int r = 0; r < ROWS_PER_WARP; r++) {
        const int b = ROWS_PER_WARP * gw + r;

        const float4* __restrict__ sup4 = reinterpret_cast<const float4*>(
            support + (size_t)b * N_SUP * D_DIM);

        // Label masks: 2 coalesced loads + 2 ballots.
        const int lbase = b * N_SUP;
        const unsigned m0 = __ballot_sync(0xFFFFFFFFu, labels[lbase + lane]      == 1);
        const unsigned m1 = __ballot_sync(0xFFFFFFFFu, labels[lbase + 32 + lane] == 1);
        const int cnt = __popc(m0) + __popc(m1);

        // Fully-unrolled dual-stream predicated accumulation.
        // Lane owns dims [8*lane, 8*lane+8); enabled row = 1KB coalesced read.
        float4 a0 = make_float4(0.f, 0.f, 0.f, 0.f);
        float4 a1 = make_float4(0.f, 0.f, 0.f, 0.f);
        float4 e0 = make_float4(0.f, 0.f, 0.f, 0.f);
        float4 e1 = make_float4(0.f, 0.f, 0.f, 0.f);

        #pragma unroll
        for (int n = 0; n < 32; n++) {
            if ((m0 >> n) & 1u) {
                float4 v0 = __ldcs(&sup4[n * ROW_F4 + c0]);
                float4 v1 = __ldcs(&sup4[n * ROW_F4 + c0 + 1]);
                a0.x += v0.x; a0.y += v0.y; a0.z += v0.z; a0.w += v0.w;
                a1.x += v1.x; a1.y += v1.y; a1.z += v1.z; a1.w += v1.w;
            }
            if ((m1 >> n) & 1u) {
                float4 w0 = __ldcs(&sup4[(n + 32) * ROW_F4 + c0]);
                float4 w1 = __ldcs(&sup4[(n + 32) * ROW_F4 + c0 + 1]);
                e0.x += w0.x; e0.y += w0.y; e0.z += w0.z; e0.w += w0.w;
                e1.x += w1.x; e1.y += w1.y; e1.z += w1.z; e1.w += w1.w;
            }
        }
        a0.x += e0.x; a0.y += e0.y; a0.z += e0.z; a0.w += e0.w;
        a1.x += e1.x; a1.y += e1.y; a1.z += e1.z; a1.w += e1.w;

        // Prototype (count==0 fallback to support[b,0,:])
        float4 p0, p1;
        if (cnt > 0) {
            const float inv = 1.0f / (float)cnt;
            p0 = make_float4(a0.x * inv, a0.y * inv, a0.z * inv, a0.w * inv);
            p1 = make_float4(a1.x * inv, a1.y * inv, a1.z * inv, a1.w * inv);
        } else {
            p0 = sup4[c0];
            p1 = sup4[c0 + 1];
        }

        const float4* __restrict__ qry4 = reinterpret_cast<const float4*>(
            query + (size_t)b * D_DIM);
        const float4 q0 = qry4[c0];
        const float4 q1 = qry4[c0 + 1];

        float d;
        {
            float dx = q0.x - p0.x, dy = q0.y - p0.y, dz = q0.z - p0.z, dw = q0.w - p0.w;
            d = dx * dx + dy * dy + dz * dz + dw * dw;
            dx = q1.x - p1.x; dy = q1.y - p1.y; dz = q1.z - p1.z; dw = q1.w - p1.w;
            d += dx * dx + dy * dy + dz * dz + dw * dw;
        }
        #pragma unroll
        for (int off = 16; off > 0; off >>= 1)
            d += __shfl_xor_sync(0xFFFFFFFFu, d, off);

        if (lane == 0) g_dist[b] = sqrtf(d + EPS);
    }

    // ---- last-CTA mean reduce (deterministic fixed-order sum) ----
    __threadfence();
    __syncthreads();
    __shared__ int s_last;
    __shared__ float s_red[WARPS_PER_CTA];
    if (tid == 0)
        s_last = (atomicAdd(&g_counter, 1u) == (unsigned)(GRID_CTAS - 1));
    __syncthreads();

    if (s_last) {
        float s = 0.f;
        #pragma unroll
        for (int i = 0; i < B_BATCH / CTA_THREADS; i++)
            s += g_dist[tid + i * CTA_THREADS];

        #pragma unroll
        for (int off = 16; off > 0; off >>= 1)
            s += __shfl_xor_sync(0xFFFFFFFFu, s, off);
        if (lane == 0) s_red[wid] = s;
        __syncthreads();
        if (tid < WARPS_PER_CTA) {
            float w = s_red[tid];
            #pragma unroll
            for (int off = WARPS_PER_CTA / 2; off > 0; off >>= 1)
                w += __shfl_xor_sync(0xFFu, w, off);
            if (tid == 0) {
                out[0] = w * (1.0f / (float)B_BATCH);
                g_counter = 0;   // reset for next graph replay
            }
        }
    }
}

extern "C" void kernel_launch(void* const* d_in, const int* in_sizes, int n_in,
                              void* d_out, int out_size)
{
    const float* query   = (const float*)d_in[0];
    const float* support = (const float*)d_in[1];
    const int*   labels  = (const int*)d_in[2];
    float* out = (float*)d_out;

    proto_loss_kernel<<<GRID_CTAS, CTA_THREADS>>>(query, support, labels, out);
}